// round 4
// baseline (speedup 1.0000x reference)
#include <cuda_runtime.h>
#include <cuda_bf16.h>
#include <math.h>
#include <stdint.h>

// Problem constants
#define BATCH 4
#define NTOK 4096
#define DIM 1024
#define NHEAD 16
#define HD 64
#define MROWS (BATCH * NTOK)          // 16384
#define SCALE 0.125f                  // HD^-0.5

// ---------------------------------------------------------------------------
// Scratch buffers
// ---------------------------------------------------------------------------
__device__ __nv_bfloat16 g_x_hi [MROWS * DIM];
__device__ __nv_bfloat16 g_x_lo [MROWS * DIM];
__device__ __nv_bfloat16 g_hq_hi[MROWS * DIM];
__device__ __nv_bfloat16 g_hq_lo[MROWS * DIM];
__device__ __nv_bfloat16 g_hk_hi[MROWS * DIM];
__device__ __nv_bfloat16 g_hk_lo[MROWS * DIM];
__device__ __nv_bfloat16 g_y_hi [MROWS * DIM];
__device__ __nv_bfloat16 g_y_lo [MROWS * DIM];
__device__ float g_q [MROWS * DIM];
__device__ float g_k [MROWS * DIM];
__device__ float g_v [MROWS * DIM];
__device__ float g_g [MROWS * DIM];
__device__ float g_A [BATCH * NHEAD * HD * HD];
__device__ float g_z [BATCH * NHEAD * HD];
__device__ __nv_bfloat16 g_w_hi [7 * DIM * DIM];
__device__ __nv_bfloat16 g_w_lo [7 * DIM * DIM];

// ---------------------------------------------------------------------------
// PTX helpers (sm_80+ portable)
// ---------------------------------------------------------------------------
__device__ __forceinline__ uint32_t smem_u32(const void* p) {
    uint32_t a;
    asm("{ .reg .u64 t; cvta.to.shared.u64 t, %1; cvt.u32.u64 %0, t; }" : "=r"(a) : "l"(p));
    return a;
}
#define SWZ(o) ((o) ^ (((o) >> 3) & 0x70))

__device__ __forceinline__ void cp16(uint32_t saddr, const void* g) {
    asm volatile("cp.async.cg.shared.global [%0], [%1], 16;" :: "r"(saddr), "l"(g));
}
#define CP_COMMIT() asm volatile("cp.async.commit_group;" ::: "memory")
#define CP_WAIT(N)  asm volatile("cp.async.wait_group %0;" :: "n"(N) : "memory")

#define LDSM4(r, a) \
    asm volatile("ldmatrix.sync.aligned.m8n8.x4.shared.b16 {%0,%1,%2,%3}, [%4];" \
        : "=r"((r)[0]), "=r"((r)[1]), "=r"((r)[2]), "=r"((r)[3]) : "r"(a))

#define MMA16816(c, a, b) \
    asm volatile("mma.sync.aligned.m16n8k16.row.col.f32.bf16.bf16.f32 " \
        "{%0,%1,%2,%3}, {%4,%5,%6,%7}, {%8,%9}, {%0,%1,%2,%3};" \
        : "+f"((c)[0]), "+f"((c)[1]), "+f"((c)[2]), "+f"((c)[3]) \
        : "r"((a)[0]), "r"((a)[1]), "r"((a)[2]), "r"((a)[3]), \
          "r"((b)[0]), "r"((b)[1]))

// ---------------------------------------------------------------------------
// Activations
// ---------------------------------------------------------------------------
__device__ __forceinline__ float gelu_f(float x) {
    return 0.5f * x * (1.0f + erff(x * 0.70710678118654752440f));
}
__device__ __forceinline__ float softplus_f(float x) {
    return fmaxf(x, 0.0f) + log1pf(__expf(-fabsf(x)));
}

// ---------------------------------------------------------------------------
// Split fp32 -> bf16 hi/lo
// ---------------------------------------------------------------------------
__global__ __launch_bounds__(256)
void split_fp32(const float* __restrict__ src, __nv_bfloat16* __restrict__ hi,
                __nv_bfloat16* __restrict__ lo, int n4)
{
    int i = blockIdx.x * blockDim.x + threadIdx.x;
    if (i >= n4) return;
    float4 v = ((const float4*)src)[i];
    __nv_bfloat16 h0 = __float2bfloat16(v.x), h1 = __float2bfloat16(v.y);
    __nv_bfloat16 h2 = __float2bfloat16(v.z), h3 = __float2bfloat16(v.w);
    __nv_bfloat16 l0 = __float2bfloat16(v.x - __bfloat162float(h0));
    __nv_bfloat16 l1 = __float2bfloat16(v.y - __bfloat162float(h1));
    __nv_bfloat16 l2 = __float2bfloat16(v.z - __bfloat162float(h2));
    __nv_bfloat16 l3 = __float2bfloat16(v.w - __bfloat162float(h3));
    __nv_bfloat162* hp = (__nv_bfloat162*)hi;
    __nv_bfloat162* lp = (__nv_bfloat162*)lo;
    hp[2 * i]     = __nv_bfloat162(h0, h1);
    hp[2 * i + 1] = __nv_bfloat162(h2, h3);
    lp[2 * i]     = __nv_bfloat162(l0, l1);
    lp[2 * i + 1] = __nv_bfloat162(l2, l3);
}

// ---------------------------------------------------------------------------
// HMMA split-bf16 GEMM: C[M,1024] = act(A @ W^T + bias)
// CTA tile 128x128, BK=64, 3-stage cp.async pipeline, 16 warps (4m x 4n),
// warp tile 32x32.
// ---------------------------------------------------------------------------
#define TILE_B 16384               // one 128x64 bf16 tile
#define STAGE_B (4 * TILE_B)       // Ahi, Alo, Whi, Wlo
#define NSTAGE 3
#define GSMEM_TOTAL (NSTAGE * STAGE_B)   // 196608

__global__ __launch_bounds__(512, 1)
void gemm_mma(const __nv_bfloat16* __restrict__ Ahi, const __nv_bfloat16* __restrict__ Alo,
              const __nv_bfloat16* __restrict__ Whi, const __nv_bfloat16* __restrict__ Wlo,
              const float* __restrict__ bias, int act, int outmode,
              float* __restrict__ Cf, __nv_bfloat16* __restrict__ Chi,
              __nv_bfloat16* __restrict__ Clo)
{
    extern __shared__ char smem[];
    const uint32_t sb = smem_u32(smem);
    const int t    = threadIdx.x;
    const int lane = t & 31;
    const int w    = t >> 5;       // 0..15
    const int wm   = w & 3;        // 4 m-warps
    const int wn   = w >> 2;       // 4 n-warps
    const int m0   = blockIdx.y * 128;
    const int n0   = blockIdx.x * 128;

    const int lrow = t >> 3;       // 0..63
    const int lu   = t & 7;

    auto issue = [&](int stage, int kc) {
        const uint32_t sbase = sb + stage * STAGE_B;
        const int kbase = kc * 64 + lu * 8;
#pragma unroll
        for (int i = 0; i < 2; i++) {
            const int row = lrow + i * 64;
            const uint32_t soff = SWZ((uint32_t)(row * 128 + lu * 16));
            const size_t aoff = (size_t)(m0 + row) * DIM + kbase;
            const size_t woff = (size_t)(n0 + row) * DIM + kbase;
            cp16(sbase + soff,              Ahi + aoff);
            cp16(sbase + TILE_B + soff,     Alo + aoff);
            cp16(sbase + 2 * TILE_B + soff, Whi + woff);
            cp16(sbase + 3 * TILE_B + soff, Wlo + woff);
        }
        CP_COMMIT();
    };

    issue(0, 0);
    issue(1, 1);

    float acc[2][4][4];
#pragma unroll
    for (int im = 0; im < 2; im++)
#pragma unroll
        for (int in = 0; in < 4; in++)
#pragma unroll
            for (int j = 0; j < 4; j++) acc[im][in][j] = 0.0f;

    const int g  = lane >> 3;     // ldmatrix group 0..3
    const int rr = lane & 7;

    for (int kc = 0; kc < 16; kc++) {
        if (kc == 15) { CP_WAIT(0); } else { CP_WAIT(1); }
        __syncthreads();
        if (kc + 2 < 16) issue((kc + 2) % NSTAGE, kc + 2);

        const uint32_t st  = sb + (kc % NSTAGE) * STAGE_B;
        const uint32_t stA = st;
        const uint32_t stAl = st + TILE_B;
        const uint32_t stW = st + 2 * TILE_B;
        const uint32_t stWl = st + 3 * TILE_B;
#pragma unroll
        for (int kk = 0; kk < 4; kk++) {
            const int ku = kk * 2 + (g >> 1);
            uint32_t ah[2][4], al[2][4];
#pragma unroll
            for (int im = 0; im < 2; im++) {
                const int row = wm * 32 + im * 16 + (g & 1) * 8 + rr;
                const uint32_t off = SWZ((uint32_t)(row * 128 + ku * 16));
                LDSM4(ah[im], stA + off);
                LDSM4(al[im], stAl + off);
            }
            uint32_t bh[4][2], bl[4][2];
#pragma unroll
            for (int in2 = 0; in2 < 2; in2++) {
                const int row = wn * 32 + in2 * 16 + (g & 1) * 8 + rr;
                const uint32_t off = SWZ((uint32_t)(row * 128 + ku * 16));
                uint32_t qh[4], ql[4];
                LDSM4(qh, stW + off);
                LDSM4(ql, stWl + off);
                bh[2 * in2][0] = qh[0]; bh[2 * in2][1] = qh[2];
                bh[2 * in2 + 1][0] = qh[1]; bh[2 * in2 + 1][1] = qh[3];
                bl[2 * in2][0] = ql[0]; bl[2 * in2][1] = ql[2];
                bl[2 * in2 + 1][0] = ql[1]; bl[2 * in2 + 1][1] = ql[3];
            }
#pragma unroll
            for (int im = 0; im < 2; im++)
#pragma unroll
                for (int in = 0; in < 4; in++) {
                    MMA16816(acc[im][in], ah[im], bh[in]);
                    MMA16816(acc[im][in], al[im], bh[in]);
                    MMA16816(acc[im][in], ah[im], bl[in]);
                }
        }
    }

    // ------ epilogue ------
    const int r0 = lane >> 2;
    const int c0 = (lane & 3) * 2;
#pragma unroll
    for (int im = 0; im < 2; im++) {
#pragma unroll
        for (int in = 0; in < 4; in++) {
            const int ncol = n0 + wn * 32 + in * 8 + c0;
            const float b0 = __ldg(&bias[ncol]);
            const float b1 = __ldg(&bias[ncol + 1]);
#pragma unroll
            for (int half = 0; half < 2; half++) {
                const int mrow = m0 + wm * 32 + im * 16 + r0 + half * 8;
                float v0 = acc[im][in][half * 2]     + b0;
                float v1 = acc[im][in][half * 2 + 1] + b1;
                if (act == 1)      { v0 = gelu_f(v0);     v1 = gelu_f(v1); }
                else if (act == 2) { v0 = softplus_f(v0); v1 = softplus_f(v1); }
                if (outmode == 0) {
                    *(float2*)(Cf + (size_t)mrow * DIM + ncol) = make_float2(v0, v1);
                } else {
                    __nv_bfloat16 h0 = __float2bfloat16(v0);
                    __nv_bfloat16 h1 = __float2bfloat16(v1);
                    __nv_bfloat16 l0 = __float2bfloat16(v0 - __bfloat162float(h0));
                    __nv_bfloat16 l1 = __float2bfloat16(v1 - __bfloat162float(h1));
                    *(__nv_bfloat162*)(Chi + (size_t)mrow * DIM + ncol) = __nv_bfloat162(h0, h1);
                    *(__nv_bfloat162*)(Clo + (size_t)mrow * DIM + ncol) = __nv_bfloat162(l0, l1);
                }
            }
        }
    }
}

// ---------------------------------------------------------------------------
// Attention pass 1
// ---------------------------------------------------------------------------
__global__ __launch_bounds__(512)
void attn_pass1(const float* __restrict__ q, const float* __restrict__ k,
                float* __restrict__ gA, float* __restrict__ gZ)
{
    const int bh = blockIdx.x;
    const int b  = bh >> 4;
    const int h  = bh & 15;
    const float* qb = q + (size_t)b * NTOK * DIM + h * HD;
    const float* kb = k + (size_t)b * NTOK * DIM + h * HD;

    __shared__ float qs[64][64];
    __shared__ float ks[64][64];
    __shared__ float ksum[64];

    const int t  = threadIdx.x;
    const int n  = t >> 3;
    const int m0 = (t & 7) << 3;
    const int lr = t >> 3;
    const int lc = (t & 7) << 3;

    float acc[8] = {0, 0, 0, 0, 0, 0, 0, 0};
    float zacc = 0.0f;
    const bool zowner = ((t & 7) == 0);

    for (int c0 = 0; c0 < NTOK; c0 += 64) {
        const float* qrow = qb + (size_t)(c0 + lr) * DIM + lc;
        const float* krow = kb + (size_t)(c0 + lr) * DIM + lc;
        float4 qa = *(const float4*)(qrow);
        float4 qc = *(const float4*)(qrow + 4);
        float4 ka = *(const float4*)(krow);
        float4 kc = *(const float4*)(krow + 4);
        __syncthreads();
        *(float4*)&qs[lr][lc]     = qa;
        *(float4*)&qs[lr][lc + 4] = qc;
        *(float4*)&ks[lr][lc]     = ka;
        *(float4*)&ks[lr][lc + 4] = kc;
        __syncthreads();
        if (t < 64) {
            float s = 0.0f;
#pragma unroll
            for (int m = 0; m < 64; m++) s += ks[t][(m + t) & 63];
            ksum[t] = s;
        }
        __syncthreads();

#pragma unroll 4
        for (int c = 0; c < 64; c++) {
            float qv = qs[c][n];
            float4 k4a = *(const float4*)&ks[c][m0];
            float4 k4b = *(const float4*)&ks[c][m0 + 4];
            acc[0] += qv * k4a.x; acc[1] += qv * k4a.y;
            acc[2] += qv * k4a.z; acc[3] += qv * k4a.w;
            acc[4] += qv * k4b.x; acc[5] += qv * k4b.y;
            acc[6] += qv * k4b.z; acc[7] += qv * k4b.w;
            if (zowner) zacc += qv * ksum[c];
        }
    }

    float* Abh = gA + (size_t)bh * HD * HD;
#pragma unroll
    for (int j = 0; j < 8; j++)
        Abh[(m0 + j) * HD + n] = acc[j];
    if (zowner)
        gZ[bh * HD + n] = 1.0f / (SCALE * zacc + (float)DIM);
}

// ---------------------------------------------------------------------------
// Attention pass 2 — writes scrambled gated output as bf16 hi/lo
// ---------------------------------------------------------------------------
__global__ __launch_bounds__(256)
void attn_pass2(const float* __restrict__ v, const float* __restrict__ gg,
                const float* __restrict__ gA, const float* __restrict__ gZ,
                __nv_bfloat16* __restrict__ Yhi, __nv_bfloat16* __restrict__ Ylo)
{
    const int bh = blockIdx.x;
    const int b  = bh >> 4;
    const int h  = bh & 15;
    const int c0 = blockIdx.y * 64;

    __shared__ float As[HD * HD];
    __shared__ float vs[64][64];
    __shared__ float zs[64];

    const int t = threadIdx.x;

    const float4* Asrc = (const float4*)(gA + (size_t)bh * HD * HD);
#pragma unroll
    for (int i = t; i < HD * HD / 4; i += 256)
        ((float4*)As)[i] = Asrc[i];
    if (t < 64) zs[t] = gZ[bh * HD + t];

    {
        const int lr = t >> 2;
        const int lc = (t & 3) << 4;
        const float* vrow = v + (size_t)(b * NTOK + c0 + lr) * DIM + h * HD + lc;
        *(float4*)&vs[lr][lc]      = *(const float4*)(vrow);
        *(float4*)&vs[lr][lc + 4]  = *(const float4*)(vrow + 4);
        *(float4*)&vs[lr][lc + 8]  = *(const float4*)(vrow + 8);
        *(float4*)&vs[lr][lc + 12] = *(const float4*)(vrow + 12);
    }
    __syncthreads();

    const int nloc = t & 63;
    const int dgrp = t >> 6;

    for (int d = dgrp; d < 64; d += 4) {
        float accv = 0.0f;
#pragma unroll
        for (int m = 0; m < 64; m++)
            accv += As[m * 64 + nloc] * vs[d][m];
        const int tok = c0 + d;
        float val = (SCALE * accv + vs[d][nloc]) * zs[nloc];
        val *= gg[(size_t)(b * NTOK + tok) * DIM + h * HD + nloc];
        const int row = b * NTOK + h * 256 + (tok >> 4);
        const int col = ((tok & 15) << 6) + nloc;
        __nv_bfloat16 hi = __float2bfloat16(val);
        __nv_bfloat16 lo = __float2bfloat16(val - __bfloat162float(hi));
        Yhi[(size_t)row * DIM + col] = hi;
        Ylo[(size_t)row * DIM + col] = lo;
    }
}

// ---------------------------------------------------------------------------
// Launch — stream-forked DAG
// ---------------------------------------------------------------------------
extern "C" void kernel_launch(void* const* d_in, const int* in_sizes, int n_in,
                              void* d_out, int out_size)
{
    const float* x    = (const float*)d_in[0];
    const float* q_w1 = (const float*)d_in[1];
    const float* q_b1 = (const float*)d_in[2];
    const float* q_w2 = (const float*)d_in[3];
    const float* q_b2 = (const float*)d_in[4];
    const float* k_w1 = (const float*)d_in[5];
    const float* k_b1 = (const float*)d_in[6];
    const float* k_w2 = (const float*)d_in[7];
    const float* k_b2 = (const float*)d_in[8];
    const float* v_w  = (const float*)d_in[9];
    const float* v_b  = (const float*)d_in[10];
    const float* g_w  = (const float*)d_in[11];
    const float* g_b  = (const float*)d_in[12];
    const float* p_w  = (const float*)d_in[13];
    const float* p_b  = (const float*)d_in[14];
    float* out = (float*)d_out;

    __nv_bfloat16 *xh, *xl, *hqh, *hql, *hkh, *hkl, *yh, *yl, *wh, *wl;
    float *qb, *kb, *vb, *gb, *Ab, *zb;
    cudaGetSymbolAddress((void**)&xh,  g_x_hi);
    cudaGetSymbolAddress((void**)&xl,  g_x_lo);
    cudaGetSymbolAddress((void**)&hqh, g_hq_hi);
    cudaGetSymbolAddress((void**)&hql, g_hq_lo);
    cudaGetSymbolAddress((void**)&hkh, g_hk_hi);
    cudaGetSymbolAddress((void**)&hkl, g_hk_lo);
    cudaGetSymbolAddress((void**)&yh,  g_y_hi);
    cudaGetSymbolAddress((void**)&yl,  g_y_lo);
    cudaGetSymbolAddress((void**)&wh,  g_w_hi);
    cudaGetSymbolAddress((void**)&wl,  g_w_lo);
    cudaGetSymbolAddress((void**)&qb,  g_q);
    cudaGetSymbolAddress((void**)&kb,  g_k);
    cudaGetSymbolAddress((void**)&vb,  g_v);
    cudaGetSymbolAddress((void**)&gb,  g_g);
    cudaGetSymbolAddress((void**)&Ab,  g_A);
    cudaGetSymbolAddress((void**)&zb,  g_z);

    static bool init_done = false;
    static cudaStream_t s1, s2, s3;
    static cudaEvent_t ev_x, ev_k, ev_v, ev_g;
    if (!init_done) {
        cudaFuncSetAttribute(gemm_mma, cudaFuncAttributeMaxDynamicSharedMemorySize, GSMEM_TOTAL);
        cudaStreamCreateWithFlags(&s1, cudaStreamNonBlocking);
        cudaStreamCreateWithFlags(&s2, cudaStreamNonBlocking);
        cudaStreamCreateWithFlags(&s3, cudaStreamNonBlocking);
        cudaEventCreateWithFlags(&ev_x, cudaEventDisableTiming);
        cudaEventCreateWithFlags(&ev_k, cudaEventDisableTiming);
        cudaEventCreateWithFlags(&ev_v, cudaEventDisableTiming);
        cudaEventCreateWithFlags(&ev_g, cudaEventDisableTiming);
        init_done = true;
    }

    const int WSZ = DIM * DIM;
#define WHI(i) (wh + (size_t)(i) * WSZ)
#define WLO(i) (wl + (size_t)(i) * WSZ)
    const int WGRID = (WSZ / 4 + 255) / 256;

    dim3 ggrid(DIM / 128, MROWS / 128);   // (8, 128)

    // stream0: split x, then fork
    split_fp32<<<(MROWS * DIM / 4 + 255) / 256, 256>>>(x, xh, xl, MROWS * DIM / 4);
    cudaEventRecord(ev_x, 0);

    // --- s1: k path ---
    cudaStreamWaitEvent(s1, ev_x, 0);
    split_fp32<<<WGRID, 256, 0, s1>>>(k_w1, WHI(2), WLO(2), WSZ / 4);
    gemm_mma<<<ggrid, 512, GSMEM_TOTAL, s1>>>(xh, xl, WHI(2), WLO(2), k_b1, 1, 1, nullptr, hkh, hkl);
    split_fp32<<<WGRID, 256, 0, s1>>>(k_w2, WHI(3), WLO(3), WSZ / 4);
    gemm_mma<<<ggrid, 512, GSMEM_TOTAL, s1>>>(hkh, hkl, WHI(3), WLO(3), k_b2, 2, 0, kb, nullptr, nullptr);
    cudaEventRecord(ev_k, s1);

    // --- s2: v ---
    cudaStreamWaitEvent(s2, ev_x, 0);
    split_fp32<<<WGRID, 256, 0, s2>>>(v_w, WHI(4), WLO(4), WSZ / 4);
    gemm_mma<<<ggrid, 512, GSMEM_TOTAL, s2>>>(xh, xl, WHI(4), WLO(4), v_b, 1, 0, vb, nullptr, nullptr);
    cudaEventRecord(ev_v, s2);

    // --- s3: g ---
    cudaStreamWaitEvent(s3, ev_x, 0);
    split_fp32<<<WGRID, 256, 0, s3>>>(g_w, WHI(5), WLO(5), WSZ / 4);
    gemm_mma<<<ggrid, 512, GSMEM_TOTAL, s3>>>(xh, xl, WHI(5), WLO(5), g_b, 1, 0, gb, nullptr, nullptr);
    cudaEventRecord(ev_g, s3);

    // --- stream0: q path ---
    split_fp32<<<WGRID, 256>>>(q_w1, WHI(0), WLO(0), WSZ / 4);
    gemm_mma<<<ggrid, 512, GSMEM_TOTAL>>>(xh, xl, WHI(0), WLO(0), q_b1, 1, 1, nullptr, hqh, hql);
    split_fp32<<<WGRID, 256>>>(q_w2, WHI(1), WLO(1), WSZ / 4);
    gemm_mma<<<ggrid, 512, GSMEM_TOTAL>>>(hqh, hql, WHI(1), WLO(1), q_b2, 2, 0, qb, nullptr, nullptr);
    split_fp32<<<WGRID, 256>>>(p_w, WHI(6), WLO(6), WSZ / 4);

    // join k for attention pass 1
    cudaStreamWaitEvent(0, ev_k, 0);
    attn_pass1<<<BATCH * NHEAD, 512>>>(qb, kb, Ab, zb);
    // join v, g for pass 2
    cudaStreamWaitEvent(0, ev_v, 0);
    cudaStreamWaitEvent(0, ev_g, 0);
    attn_pass2<<<dim3(BATCH * NHEAD, NTOK / 64), 256>>>(vb, gb, Ab, zb, yh, yl);

    // final projection
    gemm_mma<<<ggrid, 512, GSMEM_TOTAL>>>(yh, yl, WHI(6), WLO(6), p_b, 0, 0, out, nullptr, nullptr);
}

// round 5
// speedup vs baseline: 1.8318x; 1.8318x over previous
#include <cuda_runtime.h>
#include <cuda_fp16.h>
#include <cuda_bf16.h>
#include <math.h>
#include <stdint.h>

// Problem constants
#define BATCH 4
#define NTOK 4096
#define DIM 1024
#define NHEAD 16
#define HD 64
#define MROWS (BATCH * NTOK)          // 16384
#define SCALE 0.125f                  // HD^-0.5

// ---------------------------------------------------------------------------
// Scratch buffers
// ---------------------------------------------------------------------------
__device__ __half g_x_hi [MROWS * DIM];
__device__ __half g_x_lo [MROWS * DIM];
__device__ __half g_h_hi [MROWS * DIM];
__device__ __half g_h_lo [MROWS * DIM];
__device__ __half g_y_hi [MROWS * DIM];
__device__ __half g_y_lo [MROWS * DIM];
__device__ float g_q [MROWS * DIM];
__device__ float g_k [MROWS * DIM];
__device__ float g_v [MROWS * DIM];
__device__ float g_g [MROWS * DIM];
__device__ float g_A [BATCH * NHEAD * HD * HD];
__device__ float g_z [BATCH * NHEAD * HD];
__device__ __half g_w_h [7 * DIM * DIM];   // fp16 weights (hi only)

// ---------------------------------------------------------------------------
// PTX helpers (sm_80+ portable)
// ---------------------------------------------------------------------------
__device__ __forceinline__ uint32_t smem_u32(const void* p) {
    uint32_t a;
    asm("{ .reg .u64 t; cvta.to.shared.u64 t, %1; cvt.u32.u64 %0, t; }" : "=r"(a) : "l"(p));
    return a;
}
#define SWZ(o) ((o) ^ (((o) >> 3) & 0x70))

__device__ __forceinline__ void cp16(uint32_t saddr, const void* g) {
    asm volatile("cp.async.cg.shared.global [%0], [%1], 16;" :: "r"(saddr), "l"(g));
}
#define CP_COMMIT() asm volatile("cp.async.commit_group;" ::: "memory")
#define CP_WAIT(N)  asm volatile("cp.async.wait_group %0;" :: "n"(N) : "memory")

#define LDSM4(r, a) \
    asm volatile("ldmatrix.sync.aligned.m8n8.x4.shared.b16 {%0,%1,%2,%3}, [%4];" \
        : "=r"((r)[0]), "=r"((r)[1]), "=r"((r)[2]), "=r"((r)[3]) : "r"(a))

#define MMA16816F(c, a, b) \
    asm volatile("mma.sync.aligned.m16n8k16.row.col.f32.f16.f16.f32 " \
        "{%0,%1,%2,%3}, {%4,%5,%6,%7}, {%8,%9}, {%0,%1,%2,%3};" \
        : "+f"((c)[0]), "+f"((c)[1]), "+f"((c)[2]), "+f"((c)[3]) \
        : "r"((a)[0]), "r"((a)[1]), "r"((a)[2]), "r"((a)[3]), \
          "r"((b)[0]), "r"((b)[1]))

// ---------------------------------------------------------------------------
// Activations
// ---------------------------------------------------------------------------
__device__ __forceinline__ float gelu_f(float x) {
    return 0.5f * x * (1.0f + erff(x * 0.70710678118654752440f));
}
__device__ __forceinline__ float softplus_f(float x) {
    return fmaxf(x, 0.0f) + log1pf(__expf(-fabsf(x)));
}

// ---------------------------------------------------------------------------
// Split fp32 activations -> fp16 hi/lo pair
// ---------------------------------------------------------------------------
__global__ __launch_bounds__(256)
void split_act(const float* __restrict__ src, __half* __restrict__ hi,
               __half* __restrict__ lo, int n4)
{
    int i = blockIdx.x * blockDim.x + threadIdx.x;
    if (i >= n4) return;
    float4 v = ((const float4*)src)[i];
    __half h0 = __float2half_rn(v.x), h1 = __float2half_rn(v.y);
    __half h2 = __float2half_rn(v.z), h3 = __float2half_rn(v.w);
    __half l0 = __float2half_rn(v.x - __half2float(h0));
    __half l1 = __float2half_rn(v.y - __half2float(h1));
    __half l2 = __float2half_rn(v.z - __half2float(h2));
    __half l3 = __float2half_rn(v.w - __half2float(h3));
    __half2* hp = (__half2*)hi;
    __half2* lp = (__half2*)lo;
    hp[2 * i]     = __halves2half2(h0, h1);
    hp[2 * i + 1] = __halves2half2(h2, h3);
    lp[2 * i]     = __halves2half2(l0, l1);
    lp[2 * i + 1] = __halves2half2(l2, l3);
}

// fp32 weight -> fp16 (hi only)
__global__ __launch_bounds__(256)
void conv_w(const float* __restrict__ src, __half* __restrict__ dst, int n4)
{
    int i = blockIdx.x * blockDim.x + threadIdx.x;
    if (i >= n4) return;
    float4 v = ((const float4*)src)[i];
    __half2* dp = (__half2*)dst;
    dp[2 * i]     = __halves2half2(__float2half_rn(v.x), __float2half_rn(v.y));
    dp[2 * i + 1] = __halves2half2(__float2half_rn(v.z), __float2half_rn(v.w));
}

// ---------------------------------------------------------------------------
// HMMA fp16 2-term GEMM: C[M,1024] = act((Ahi+Alo) @ Wh^T + bias)
// CTA tile 128x128, BK=64, 3-stage cp.async pipeline, 8 warps (4m x 2n),
// warp tile 32x64  (exact R3 structure, minus the Wlo tile/term).
// ---------------------------------------------------------------------------
#define TILE_B 16384               // one 128x64 fp16 tile
#define STAGE_B (3 * TILE_B)       // Ahi, Alo, Wh
#define NSTAGE 3
#define GSMEM_TOTAL (NSTAGE * STAGE_B)   // 147456

__global__ __launch_bounds__(256, 1)
void gemm_mma(const __half* __restrict__ Ahi, const __half* __restrict__ Alo,
              const __half* __restrict__ Wh,
              const float* __restrict__ bias, int act, int outmode,
              float* __restrict__ Cf, __half* __restrict__ Chi,
              __half* __restrict__ Clo)
{
    extern __shared__ char smem[];
    const uint32_t sb = smem_u32(smem);
    const int t    = threadIdx.x;
    const int lane = t & 31;
    const int w    = t >> 5;
    const int wm   = w & 3;        // 4 m-warps
    const int wn   = w >> 2;       // 2 n-warps
    const int m0   = blockIdx.y * 128;
    const int n0   = blockIdx.x * 128;

    const int lrow = t >> 3;       // 0..31
    const int lu   = t & 7;

    auto issue = [&](int stage, int kc) {
        const uint32_t sbase = sb + stage * STAGE_B;
        const int kbase = kc * 64 + lu * 8;
#pragma unroll
        for (int i = 0; i < 4; i++) {
            const int row = lrow + i * 32;
            const uint32_t soff = SWZ((uint32_t)(row * 128 + lu * 16));
            const size_t aoff = (size_t)(m0 + row) * DIM + kbase;
            const size_t woff = (size_t)(n0 + row) * DIM + kbase;
            cp16(sbase + soff,              Ahi + aoff);
            cp16(sbase + TILE_B + soff,     Alo + aoff);
            cp16(sbase + 2 * TILE_B + soff, Wh  + woff);
        }
        CP_COMMIT();
    };

    issue(0, 0);
    issue(1, 1);

    float acc[2][8][4];
#pragma unroll
    for (int im = 0; im < 2; im++)
#pragma unroll
        for (int in = 0; in < 8; in++)
#pragma unroll
            for (int j = 0; j < 4; j++) acc[im][in][j] = 0.0f;

    const int g  = lane >> 3;     // ldmatrix group 0..3
    const int rr = lane & 7;

    for (int kc = 0; kc < 16; kc++) {
        if (kc == 15) { CP_WAIT(0); } else { CP_WAIT(1); }
        __syncthreads();
        if (kc + 2 < 16) issue((kc + 2) % NSTAGE, kc + 2);

        const uint32_t st = sb + (kc % NSTAGE) * STAGE_B;
#pragma unroll
        for (int kk = 0; kk < 4; kk++) {
            const int ku = kk * 2 + (g >> 1);
            uint32_t ah[2][4], al[2][4];
#pragma unroll
            for (int im = 0; im < 2; im++) {
                const int row = wm * 32 + im * 16 + (g & 1) * 8 + rr;
                const uint32_t off = SWZ((uint32_t)(row * 128 + ku * 16));
                LDSM4(ah[im], st + off);
                LDSM4(al[im], st + TILE_B + off);
            }
            uint32_t bh[8][2];
#pragma unroll
            for (int in2 = 0; in2 < 4; in2++) {
                const int row = wn * 64 + in2 * 16 + (g & 1) * 8 + rr;
                const uint32_t off = SWZ((uint32_t)(row * 128 + ku * 16));
                uint32_t qh[4];
                LDSM4(qh, st + 2 * TILE_B + off);
                bh[2 * in2][0] = qh[0]; bh[2 * in2][1] = qh[2];
                bh[2 * in2 + 1][0] = qh[1]; bh[2 * in2 + 1][1] = qh[3];
            }
#pragma unroll
            for (int im = 0; im < 2; im++)
#pragma unroll
                for (int in = 0; in < 8; in++) {
                    MMA16816F(acc[im][in], ah[im], bh[in]);
                    MMA16816F(acc[im][in], al[im], bh[in]);
                }
        }
    }

    // ------ epilogue ------
    const int r0 = lane >> 2;
    const int c0 = (lane & 3) * 2;
#pragma unroll
    for (int im = 0; im < 2; im++) {
#pragma unroll
        for (int in = 0; in < 8; in++) {
            const int ncol = n0 + wn * 64 + in * 8 + c0;
            const float b0 = __ldg(&bias[ncol]);
            const float b1 = __ldg(&bias[ncol + 1]);
#pragma unroll
            for (int half = 0; half < 2; half++) {
                const int mrow = m0 + wm * 32 + im * 16 + r0 + half * 8;
                float v0 = acc[im][in][half * 2]     + b0;
                float v1 = acc[im][in][half * 2 + 1] + b1;
                if (act == 1)      { v0 = gelu_f(v0);     v1 = gelu_f(v1); }
                else if (act == 2) { v0 = softplus_f(v0); v1 = softplus_f(v1); }
                if (outmode == 0) {
                    *(float2*)(Cf + (size_t)mrow * DIM + ncol) = make_float2(v0, v1);
                } else {
                    __half h0 = __float2half_rn(v0);
                    __half h1 = __float2half_rn(v1);
                    __half l0 = __float2half_rn(v0 - __half2float(h0));
                    __half l1 = __float2half_rn(v1 - __half2float(h1));
                    *(__half2*)(Chi + (size_t)mrow * DIM + ncol) = __halves2half2(h0, h1);
                    *(__half2*)(Clo + (size_t)mrow * DIM + ncol) = __halves2half2(l0, l1);
                }
            }
        }
    }
}

// ---------------------------------------------------------------------------
// Attention pass 1
// ---------------------------------------------------------------------------
__global__ __launch_bounds__(512)
void attn_pass1(const float* __restrict__ q, const float* __restrict__ k,
                float* __restrict__ gA, float* __restrict__ gZ)
{
    const int bh = blockIdx.x;
    const int b  = bh >> 4;
    const int h  = bh & 15;
    const float* qb = q + (size_t)b * NTOK * DIM + h * HD;
    const float* kb = k + (size_t)b * NTOK * DIM + h * HD;

    __shared__ float qs[64][64];
    __shared__ float ks[64][64];
    __shared__ float ksum[64];

    const int t  = threadIdx.x;
    const int n  = t >> 3;
    const int m0 = (t & 7) << 3;
    const int lr = t >> 3;
    const int lc = (t & 7) << 3;

    float acc[8] = {0, 0, 0, 0, 0, 0, 0, 0};
    float zacc = 0.0f;
    const bool zowner = ((t & 7) == 0);

    for (int c0 = 0; c0 < NTOK; c0 += 64) {
        const float* qrow = qb + (size_t)(c0 + lr) * DIM + lc;
        const float* krow = kb + (size_t)(c0 + lr) * DIM + lc;
        float4 qa = *(const float4*)(qrow);
        float4 qc = *(const float4*)(qrow + 4);
        float4 ka = *(const float4*)(krow);
        float4 kc = *(const float4*)(krow + 4);
        __syncthreads();
        *(float4*)&qs[lr][lc]     = qa;
        *(float4*)&qs[lr][lc + 4] = qc;
        *(float4*)&ks[lr][lc]     = ka;
        *(float4*)&ks[lr][lc + 4] = kc;
        __syncthreads();
        if (t < 64) {
            float s = 0.0f;
#pragma unroll
            for (int m = 0; m < 64; m++) s += ks[t][(m + t) & 63];
            ksum[t] = s;
        }
        __syncthreads();

#pragma unroll 4
        for (int c = 0; c < 64; c++) {
            float qv = qs[c][n];
            float4 k4a = *(const float4*)&ks[c][m0];
            float4 k4b = *(const float4*)&ks[c][m0 + 4];
            acc[0] += qv * k4a.x; acc[1] += qv * k4a.y;
            acc[2] += qv * k4a.z; acc[3] += qv * k4a.w;
            acc[4] += qv * k4b.x; acc[5] += qv * k4b.y;
            acc[6] += qv * k4b.z; acc[7] += qv * k4b.w;
            if (zowner) zacc += qv * ksum[c];
        }
    }

    float* Abh = gA + (size_t)bh * HD * HD;
#pragma unroll
    for (int j = 0; j < 8; j++)
        Abh[(m0 + j) * HD + n] = acc[j];
    if (zowner)
        gZ[bh * HD + n] = 1.0f / (SCALE * zacc + (float)DIM);
}

// ---------------------------------------------------------------------------
// Attention pass 2 — writes scrambled gated output as fp16 hi/lo
// ---------------------------------------------------------------------------
__global__ __launch_bounds__(256)
void attn_pass2(const float* __restrict__ v, const float* __restrict__ gg,
                const float* __restrict__ gA, const float* __restrict__ gZ,
                __half* __restrict__ Yhi, __half* __restrict__ Ylo)
{
    const int bh = blockIdx.x;
    const int b  = bh >> 4;
    const int h  = bh & 15;
    const int c0 = blockIdx.y * 64;

    __shared__ float As[HD * HD];
    __shared__ float vs[64][64];
    __shared__ float zs[64];

    const int t = threadIdx.x;

    const float4* Asrc = (const float4*)(gA + (size_t)bh * HD * HD);
#pragma unroll
    for (int i = t; i < HD * HD / 4; i += 256)
        ((float4*)As)[i] = Asrc[i];
    if (t < 64) zs[t] = gZ[bh * HD + t];

    {
        const int lr = t >> 2;
        const int lc = (t & 3) << 4;
        const float* vrow = v + (size_t)(b * NTOK + c0 + lr) * DIM + h * HD + lc;
        *(float4*)&vs[lr][lc]      = *(const float4*)(vrow);
        *(float4*)&vs[lr][lc + 4]  = *(const float4*)(vrow + 4);
        *(float4*)&vs[lr][lc + 8]  = *(const float4*)(vrow + 8);
        *(float4*)&vs[lr][lc + 12] = *(const float4*)(vrow + 12);
    }
    __syncthreads();

    const int nloc = t & 63;
    const int dgrp = t >> 6;

    for (int d = dgrp; d < 64; d += 4) {
        float accv = 0.0f;
#pragma unroll
        for (int m = 0; m < 64; m++)
            accv += As[m * 64 + nloc] * vs[d][m];
        const int tok = c0 + d;
        float val = (SCALE * accv + vs[d][nloc]) * zs[nloc];
        val *= gg[(size_t)(b * NTOK + tok) * DIM + h * HD + nloc];
        const int row = b * NTOK + h * 256 + (tok >> 4);
        const int col = ((tok & 15) << 6) + nloc;
        __half hi = __float2half_rn(val);
        __half lo = __float2half_rn(val - __half2float(hi));
        Yhi[(size_t)row * DIM + col] = hi;
        Ylo[(size_t)row * DIM + col] = lo;
    }
}

// ---------------------------------------------------------------------------
// Launch (single stream — R3-style sequential)
// ---------------------------------------------------------------------------
extern "C" void kernel_launch(void* const* d_in, const int* in_sizes, int n_in,
                              void* d_out, int out_size)
{
    const float* x    = (const float*)d_in[0];
    const float* q_w1 = (const float*)d_in[1];
    const float* q_b1 = (const float*)d_in[2];
    const float* q_w2 = (const float*)d_in[3];
    const float* q_b2 = (const float*)d_in[4];
    const float* k_w1 = (const float*)d_in[5];
    const float* k_b1 = (const float*)d_in[6];
    const float* k_w2 = (const float*)d_in[7];
    const float* k_b2 = (const float*)d_in[8];
    const float* v_w  = (const float*)d_in[9];
    const float* v_b  = (const float*)d_in[10];
    const float* g_w  = (const float*)d_in[11];
    const float* g_b  = (const float*)d_in[12];
    const float* p_w  = (const float*)d_in[13];
    const float* p_b  = (const float*)d_in[14];
    float* out = (float*)d_out;

    __half *xh, *xl, *hh, *hl, *yh, *yl, *wh;
    float *qb, *kb, *vb, *gb, *Ab, *zb;
    cudaGetSymbolAddress((void**)&xh, g_x_hi);
    cudaGetSymbolAddress((void**)&xl, g_x_lo);
    cudaGetSymbolAddress((void**)&hh, g_h_hi);
    cudaGetSymbolAddress((void**)&hl, g_h_lo);
    cudaGetSymbolAddress((void**)&yh, g_y_hi);
    cudaGetSymbolAddress((void**)&yl, g_y_lo);
    cudaGetSymbolAddress((void**)&wh, g_w_h);
    cudaGetSymbolAddress((void**)&qb, g_q);
    cudaGetSymbolAddress((void**)&kb, g_k);
    cudaGetSymbolAddress((void**)&vb, g_v);
    cudaGetSymbolAddress((void**)&gb, g_g);
    cudaGetSymbolAddress((void**)&Ab, g_A);
    cudaGetSymbolAddress((void**)&zb, g_z);

    static bool attr_done = false;
    if (!attr_done) {
        cudaFuncSetAttribute(gemm_mma, cudaFuncAttributeMaxDynamicSharedMemorySize, GSMEM_TOTAL);
        attr_done = true;
    }

    const int WSZ = DIM * DIM;
    const int WGRID = (WSZ / 4 + 255) / 256;
#define WH(i) (wh + (size_t)(i) * WSZ)

    split_act<<<(MROWS * DIM / 4 + 255) / 256, 256>>>(x, xh, xl, MROWS * DIM / 4);
    const float* ws[7] = {q_w1, q_w2, k_w1, k_w2, v_w, g_w, p_w};
    for (int i = 0; i < 7; i++)
        conv_w<<<WGRID, 256>>>(ws[i], WH(i), WSZ / 4);

    dim3 ggrid(DIM / 128, MROWS / 128);   // (8, 128)

    // q path
    gemm_mma<<<ggrid, 256, GSMEM_TOTAL>>>(xh, xl, WH(0), q_b1, 1, 1, nullptr, hh, hl);
    gemm_mma<<<ggrid, 256, GSMEM_TOTAL>>>(hh, hl, WH(1), q_b2, 2, 0, qb, nullptr, nullptr);
    // k path
    gemm_mma<<<ggrid, 256, GSMEM_TOTAL>>>(xh, xl, WH(2), k_b1, 1, 1, nullptr, hh, hl);
    gemm_mma<<<ggrid, 256, GSMEM_TOTAL>>>(hh, hl, WH(3), k_b2, 2, 0, kb, nullptr, nullptr);
    // v, g
    gemm_mma<<<ggrid, 256, GSMEM_TOTAL>>>(xh, xl, WH(4), v_b, 1, 0, vb, nullptr, nullptr);
    gemm_mma<<<ggrid, 256, GSMEM_TOTAL>>>(xh, xl, WH(5), g_b, 1, 0, gb, nullptr, nullptr);

    // linear attention core
    attn_pass1<<<BATCH * NHEAD, 512>>>(qb, kb, Ab, zb);
    attn_pass2<<<dim3(BATCH * NHEAD, NTOK / 64), 256>>>(vb, gb, Ab, zb, yh, yl);

    // final projection
    gemm_mma<<<ggrid, 256, GSMEM_TOTAL>>>(yh, yl, WH(6), p_b, 0, 0, out, nullptr, nullptr);
}

// round 6
// speedup vs baseline: 2.0246x; 1.1053x over previous
#include <cuda_runtime.h>
#include <cuda_fp16.h>
#include <cuda_bf16.h>
#include <math.h>
#include <stdint.h>

// Problem constants
#define BATCH 4
#define NTOK 4096
#define DIM 1024
#define NHEAD 16
#define HD 64
#define MROWS (BATCH * NTOK)          // 16384
#define SCALE 0.125f                  // HD^-0.5

// ---------------------------------------------------------------------------
// Scratch buffers
// ---------------------------------------------------------------------------
__device__ __half g_x_hi [MROWS * DIM];
__device__ __half g_x_lo [MROWS * DIM];
__device__ __half g_h_hi [MROWS * DIM];
__device__ __half g_h_lo [MROWS * DIM];
__device__ __half g_y_hi [MROWS * DIM];
__device__ __half g_y_lo [MROWS * DIM];
__device__ float g_q [MROWS * DIM];
__device__ float g_k [MROWS * DIM];
__device__ float g_v [MROWS * DIM];
__device__ float g_g [MROWS * DIM];
__device__ float g_A [BATCH * NHEAD * HD * HD];
__device__ float g_z [BATCH * NHEAD * HD];
__device__ __half g_w_h [7 * DIM * DIM];   // fp16 weights

// ---------------------------------------------------------------------------
// PTX helpers (sm_80+ portable)
// ---------------------------------------------------------------------------
__device__ __forceinline__ uint32_t smem_u32(const void* p) {
    uint32_t a;
    asm("{ .reg .u64 t; cvta.to.shared.u64 t, %1; cvt.u32.u64 %0, t; }" : "=r"(a) : "l"(p));
    return a;
}
#define SWZ(o) ((o) ^ (((o) >> 3) & 0x70))

__device__ __forceinline__ void cp16(uint32_t saddr, const void* g) {
    asm volatile("cp.async.cg.shared.global [%0], [%1], 16;" :: "r"(saddr), "l"(g));
}
#define CP_COMMIT() asm volatile("cp.async.commit_group;" ::: "memory")
#define CP_WAIT(N)  asm volatile("cp.async.wait_group %0;" :: "n"(N) : "memory")

#define LDSM4(r, a) \
    asm volatile("ldmatrix.sync.aligned.m8n8.x4.shared.b16 {%0,%1,%2,%3}, [%4];" \
        : "=r"((r)[0]), "=r"((r)[1]), "=r"((r)[2]), "=r"((r)[3]) : "r"(a))

#define MMA16816F(c, a, b) \
    asm volatile("mma.sync.aligned.m16n8k16.row.col.f32.f16.f16.f32 " \
        "{%0,%1,%2,%3}, {%4,%5,%6,%7}, {%8,%9}, {%0,%1,%2,%3};" \
        : "+f"((c)[0]), "+f"((c)[1]), "+f"((c)[2]), "+f"((c)[3]) \
        : "r"((a)[0]), "r"((a)[1]), "r"((a)[2]), "r"((a)[3]), \
          "r"((b)[0]), "r"((b)[1]))

// ---------------------------------------------------------------------------
// Activations
// ---------------------------------------------------------------------------
__device__ __forceinline__ float gelu_f(float x) {
    return 0.5f * x * (1.0f + erff(x * 0.70710678118654752440f));
}
__device__ __forceinline__ float softplus_f(float x) {
    return fmaxf(x, 0.0f) + log1pf(__expf(-fabsf(x)));
}

__device__ __forceinline__ uint32_t pack2h(float a, float b) {
    __half2 h = __halves2half2(__float2half_rn(a), __float2half_rn(b));
    return *(uint32_t*)&h;
}

// ---------------------------------------------------------------------------
// Split fp32 activations -> fp16 hi/lo pair (grid-stride, 8B stores)
// ---------------------------------------------------------------------------
__global__ __launch_bounds__(256)
void split_act(const float* __restrict__ src, __half* __restrict__ hi,
               __half* __restrict__ lo, int n4)
{
    const int stride = gridDim.x * blockDim.x;
    for (int i = blockIdx.x * blockDim.x + threadIdx.x; i < n4; i += stride) {
        float4 v = ((const float4*)src)[i];
        float h0f = __half2float(__float2half_rn(v.x));
        float h1f = __half2float(__float2half_rn(v.y));
        float h2f = __half2float(__float2half_rn(v.z));
        float h3f = __half2float(__float2half_rn(v.w));
        uint2 hp, lp;
        hp.x = pack2h(v.x, v.y);
        hp.y = pack2h(v.z, v.w);
        lp.x = pack2h(v.x - h0f, v.y - h1f);
        lp.y = pack2h(v.z - h2f, v.w - h3f);
        ((uint2*)hi)[i] = hp;
        ((uint2*)lo)[i] = lp;
    }
}

// fp32 weight -> fp16
__global__ __launch_bounds__(256)
void conv_w(const float* __restrict__ src, __half* __restrict__ dst, int n4)
{
    const int stride = gridDim.x * blockDim.x;
    for (int i = blockIdx.x * blockDim.x + threadIdx.x; i < n4; i += stride) {
        float4 v = ((const float4*)src)[i];
        uint2 d;
        d.x = pack2h(v.x, v.y);
        d.y = pack2h(v.z, v.w);
        ((uint2*)dst)[i] = d;
    }
}

// ---------------------------------------------------------------------------
// HMMA fp16 2-term GEMM: C[M,1024] = act((Ahi+Alo) @ Wh^T + bias)
// CTA tile 128x128, BK=64, 2-stage cp.async pipeline, 8 warps (4m x 2n),
// warp tile 32x64. 2 CTAs/SM (96KB smem each, <=128 regs).
// ---------------------------------------------------------------------------
#define TILE_B 16384               // one 128x64 fp16 tile
#define STAGE_B (3 * TILE_B)       // Ahi, Alo, Wh
#define NSTAGE 2
#define GSMEM_TOTAL (NSTAGE * STAGE_B)   // 98304

__global__ __launch_bounds__(256, 2)
void gemm_mma(const __half* __restrict__ Ahi, const __half* __restrict__ Alo,
              const __half* __restrict__ Wh,
              const float* __restrict__ bias, int act, int outmode,
              float* __restrict__ Cf, __half* __restrict__ Chi,
              __half* __restrict__ Clo)
{
    extern __shared__ char smem[];
    const uint32_t sb = smem_u32(smem);
    const int t    = threadIdx.x;
    const int lane = t & 31;
    const int w    = t >> 5;
    const int wm   = w & 3;        // 4 m-warps
    const int wn   = w >> 2;       // 2 n-warps
    const int m0   = blockIdx.y * 128;
    const int n0   = blockIdx.x * 128;

    const int lrow = t >> 3;       // 0..31
    const int lu   = t & 7;

    auto issue = [&](int stage, int kc) {
        const uint32_t sbase = sb + stage * STAGE_B;
        const int kbase = kc * 64 + lu * 8;
#pragma unroll
        for (int i = 0; i < 4; i++) {
            const int row = lrow + i * 32;
            const uint32_t soff = SWZ((uint32_t)(row * 128 + lu * 16));
            const size_t aoff = (size_t)(m0 + row) * DIM + kbase;
            const size_t woff = (size_t)(n0 + row) * DIM + kbase;
            cp16(sbase + soff,              Ahi + aoff);
            cp16(sbase + TILE_B + soff,     Alo + aoff);
            cp16(sbase + 2 * TILE_B + soff, Wh  + woff);
        }
        CP_COMMIT();
    };

    issue(0, 0);
    issue(1, 1);

    float acc[2][8][4];
#pragma unroll
    for (int im = 0; im < 2; im++)
#pragma unroll
        for (int in = 0; in < 8; in++)
#pragma unroll
            for (int j = 0; j < 4; j++) acc[im][in][j] = 0.0f;

    const int g  = lane >> 3;     // ldmatrix group 0..3
    const int rr = lane & 7;

    for (int kc = 0; kc < 16; kc++) {
        const int st_idx = kc & 1;
        if (kc == 15) { CP_WAIT(0); } else { CP_WAIT(1); }
        __syncthreads();

        const uint32_t st = sb + st_idx * STAGE_B;
#pragma unroll
        for (int kk = 0; kk < 4; kk++) {
            const int ku = kk * 2 + (g >> 1);
            uint32_t ah[2][4], al[2][4];
#pragma unroll
            for (int im = 0; im < 2; im++) {
                const int row = wm * 32 + im * 16 + (g & 1) * 8 + rr;
                const uint32_t off = SWZ((uint32_t)(row * 128 + ku * 16));
                LDSM4(ah[im], st + off);
                LDSM4(al[im], st + TILE_B + off);
            }
            uint32_t bh[8][2];
#pragma unroll
            for (int in2 = 0; in2 < 4; in2++) {
                const int row = wn * 64 + in2 * 16 + (g & 1) * 8 + rr;
                const uint32_t off = SWZ((uint32_t)(row * 128 + ku * 16));
                uint32_t qh[4];
                LDSM4(qh, st + 2 * TILE_B + off);
                bh[2 * in2][0] = qh[0]; bh[2 * in2][1] = qh[2];
                bh[2 * in2 + 1][0] = qh[1]; bh[2 * in2 + 1][1] = qh[3];
            }
#pragma unroll
            for (int im = 0; im < 2; im++)
#pragma unroll
                for (int in = 0; in < 8; in++) {
                    MMA16816F(acc[im][in], ah[im], bh[in]);
                    MMA16816F(acc[im][in], al[im], bh[in]);
                }
        }

        // all warps done reading this stage before it is overwritten
        if (kc + 2 < 16) {
            __syncthreads();
            issue(st_idx, kc + 2);
        }
    }

    // ------ epilogue ------
    const int r0 = lane >> 2;
    const int c0 = (lane & 3) * 2;
#pragma unroll
    for (int im = 0; im < 2; im++) {
#pragma unroll
        for (int in = 0; in < 8; in++) {
            const int ncol = n0 + wn * 64 + in * 8 + c0;
            const float b0 = __ldg(&bias[ncol]);
            const float b1 = __ldg(&bias[ncol + 1]);
#pragma unroll
            for (int half = 0; half < 2; half++) {
                const int mrow = m0 + wm * 32 + im * 16 + r0 + half * 8;
                float v0 = acc[im][in][half * 2]     + b0;
                float v1 = acc[im][in][half * 2 + 1] + b1;
                if (act == 1)      { v0 = gelu_f(v0);     v1 = gelu_f(v1); }
                else if (act == 2) { v0 = softplus_f(v0); v1 = softplus_f(v1); }
                if (outmode == 0) {
                    *(float2*)(Cf + (size_t)mrow * DIM + ncol) = make_float2(v0, v1);
                } else {
                    __half h0 = __float2half_rn(v0);
                    __half h1 = __float2half_rn(v1);
                    __half l0 = __float2half_rn(v0 - __half2float(h0));
                    __half l1 = __float2half_rn(v1 - __half2float(h1));
                    *(__half2*)(Chi + (size_t)mrow * DIM + ncol) = __halves2half2(h0, h1);
                    *(__half2*)(Clo + (size_t)mrow * DIM + ncol) = __halves2half2(l0, l1);
                }
            }
        }
    }
}

// ---------------------------------------------------------------------------
// Attention pass 1
// ---------------------------------------------------------------------------
__global__ __launch_bounds__(512)
void attn_pass1(const float* __restrict__ q, const float* __restrict__ k,
                float* __restrict__ gA, float* __restrict__ gZ)
{
    const int bh = blockIdx.x;
    const int b  = bh >> 4;
    const int h  = bh & 15;
    const float* qb = q + (size_t)b * NTOK * DIM + h * HD;
    const float* kb = k + (size_t)b * NTOK * DIM + h * HD;

    __shared__ float qs[64][64];
    __shared__ float ks[64][64];
    __shared__ float ksum[64];

    const int t  = threadIdx.x;
    const int n  = t >> 3;
    const int m0 = (t & 7) << 3;
    const int lr = t >> 3;
    const int lc = (t & 7) << 3;

    float acc[8] = {0, 0, 0, 0, 0, 0, 0, 0};
    float zacc = 0.0f;
    const bool zowner = ((t & 7) == 0);

    for (int c0 = 0; c0 < NTOK; c0 += 64) {
        const float* qrow = qb + (size_t)(c0 + lr) * DIM + lc;
        const float* krow = kb + (size_t)(c0 + lr) * DIM + lc;
        float4 qa = *(const float4*)(qrow);
        float4 qc = *(const float4*)(qrow + 4);
        float4 ka = *(const float4*)(krow);
        float4 kc = *(const float4*)(krow + 4);
        __syncthreads();
        *(float4*)&qs[lr][lc]     = qa;
        *(float4*)&qs[lr][lc + 4] = qc;
        *(float4*)&ks[lr][lc]     = ka;
        *(float4*)&ks[lr][lc + 4] = kc;
        __syncthreads();
        if (t < 64) {
            float s = 0.0f;
#pragma unroll
            for (int m = 0; m < 64; m++) s += ks[t][(m + t) & 63];
            ksum[t] = s;
        }
        __syncthreads();

#pragma unroll 4
        for (int c = 0; c < 64; c++) {
            float qv = qs[c][n];
            float4 k4a = *(const float4*)&ks[c][m0];
            float4 k4b = *(const float4*)&ks[c][m0 + 4];
            acc[0] += qv * k4a.x; acc[1] += qv * k4a.y;
            acc[2] += qv * k4a.z; acc[3] += qv * k4a.w;
            acc[4] += qv * k4b.x; acc[5] += qv * k4b.y;
            acc[6] += qv * k4b.z; acc[7] += qv * k4b.w;
            if (zowner) zacc += qv * ksum[c];
        }
    }

    float* Abh = gA + (size_t)bh * HD * HD;
#pragma unroll
    for (int j = 0; j < 8; j++)
        Abh[(m0 + j) * HD + n] = acc[j];
    if (zowner)
        gZ[bh * HD + n] = 1.0f / (SCALE * zacc + (float)DIM);
}

// ---------------------------------------------------------------------------
// Attention pass 2 — writes scrambled gated output as fp16 hi/lo
// ---------------------------------------------------------------------------
__global__ __launch_bounds__(256)
void attn_pass2(const float* __restrict__ v, const float* __restrict__ gg,
                const float* __restrict__ gA, const float* __restrict__ gZ,
                __half* __restrict__ Yhi, __half* __restrict__ Ylo)
{
    const int bh = blockIdx.x;
    const int b  = bh >> 4;
    const int h  = bh & 15;
    const int c0 = blockIdx.y * 64;

    __shared__ float As[HD * HD];
    __shared__ float vs[64][64];
    __shared__ float zs[64];

    const int t = threadIdx.x;

    const float4* Asrc = (const float4*)(gA + (size_t)bh * HD * HD);
#pragma unroll
    for (int i = t; i < HD * HD / 4; i += 256)
        ((float4*)As)[i] = Asrc[i];
    if (t < 64) zs[t] = gZ[bh * HD + t];

    {
        const int lr = t >> 2;
        const int lc = (t & 3) << 4;
        const float* vrow = v + (size_t)(b * NTOK + c0 + lr) * DIM + h * HD + lc;
        *(float4*)&vs[lr][lc]      = *(const float4*)(vrow);
        *(float4*)&vs[lr][lc + 4]  = *(const float4*)(vrow + 4);
        *(float4*)&vs[lr][lc + 8]  = *(const float4*)(vrow + 8);
        *(float4*)&vs[lr][lc + 12] = *(const float4*)(vrow + 12);
    }
    __syncthreads();

    const int nloc = t & 63;
    const int dgrp = t >> 6;

    for (int d = dgrp; d < 64; d += 4) {
        float accv = 0.0f;
#pragma unroll
        for (int m = 0; m < 64; m++)
            accv += As[m * 64 + nloc] * vs[d][m];
        const int tok = c0 + d;
        float val = (SCALE * accv + vs[d][nloc]) * zs[nloc];
        val *= gg[(size_t)(b * NTOK + tok) * DIM + h * HD + nloc];
        const int row = b * NTOK + h * 256 + (tok >> 4);
        const int col = ((tok & 15) << 6) + nloc;
        __half hi = __float2half_rn(val);
        __half lo = __float2half_rn(val - __half2float(hi));
        Yhi[(size_t)row * DIM + col] = hi;
        Ylo[(size_t)row * DIM + col] = lo;
    }
}

// ---------------------------------------------------------------------------
// Launch (single stream, sequential)
// ---------------------------------------------------------------------------
extern "C" void kernel_launch(void* const* d_in, const int* in_sizes, int n_in,
                              void* d_out, int out_size)
{
    const float* x    = (const float*)d_in[0];
    const float* q_w1 = (const float*)d_in[1];
    const float* q_b1 = (const float*)d_in[2];
    const float* q_w2 = (const float*)d_in[3];
    const float* q_b2 = (const float*)d_in[4];
    const float* k_w1 = (const float*)d_in[5];
    const float* k_b1 = (const float*)d_in[6];
    const float* k_w2 = (const float*)d_in[7];
    const float* k_b2 = (const float*)d_in[8];
    const float* v_w  = (const float*)d_in[9];
    const float* v_b  = (const float*)d_in[10];
    const float* g_w  = (const float*)d_in[11];
    const float* g_b  = (const float*)d_in[12];
    const float* p_w  = (const float*)d_in[13];
    const float* p_b  = (const float*)d_in[14];
    float* out = (float*)d_out;

    __half *xh, *xl, *hh, *hl, *yh, *yl, *wh;
    float *qb, *kb, *vb, *gb, *Ab, *zb;
    cudaGetSymbolAddress((void**)&xh, g_x_hi);
    cudaGetSymbolAddress((void**)&xl, g_x_lo);
    cudaGetSymbolAddress((void**)&hh, g_h_hi);
    cudaGetSymbolAddress((void**)&hl, g_h_lo);
    cudaGetSymbolAddress((void**)&yh, g_y_hi);
    cudaGetSymbolAddress((void**)&yl, g_y_lo);
    cudaGetSymbolAddress((void**)&wh, g_w_h);
    cudaGetSymbolAddress((void**)&qb, g_q);
    cudaGetSymbolAddress((void**)&kb, g_k);
    cudaGetSymbolAddress((void**)&vb, g_v);
    cudaGetSymbolAddress((void**)&gb, g_g);
    cudaGetSymbolAddress((void**)&Ab, g_A);
    cudaGetSymbolAddress((void**)&zb, g_z);

    static bool attr_done = false;
    if (!attr_done) {
        cudaFuncSetAttribute(gemm_mma, cudaFuncAttributeMaxDynamicSharedMemorySize, GSMEM_TOTAL);
        attr_done = true;
    }

    const int WSZ = DIM * DIM;
#define WH(i) (wh + (size_t)(i) * WSZ)

    split_act<<<1184, 256>>>(x, xh, xl, MROWS * DIM / 4);
    const float* ws[7] = {q_w1, q_w2, k_w1, k_w2, v_w, g_w, p_w};
    for (int i = 0; i < 7; i++)
        conv_w<<<592, 256>>>(ws[i], WH(i), WSZ / 4);

    dim3 ggrid(DIM / 128, MROWS / 128);   // (8, 128)

    // q path
    gemm_mma<<<ggrid, 256, GSMEM_TOTAL>>>(xh, xl, WH(0), q_b1, 1, 1, nullptr, hh, hl);
    gemm_mma<<<ggrid, 256, GSMEM_TOTAL>>>(hh, hl, WH(1), q_b2, 2, 0, qb, nullptr, nullptr);
    // k path
    gemm_mma<<<ggrid, 256, GSMEM_TOTAL>>>(xh, xl, WH(2), k_b1, 1, 1, nullptr, hh, hl);
    gemm_mma<<<ggrid, 256, GSMEM_TOTAL>>>(hh, hl, WH(3), k_b2, 2, 0, kb, nullptr, nullptr);
    // v, g
    gemm_mma<<<ggrid, 256, GSMEM_TOTAL>>>(xh, xl, WH(4), v_b, 1, 0, vb, nullptr, nullptr);
    gemm_mma<<<ggrid, 256, GSMEM_TOTAL>>>(xh, xl, WH(5), g_b, 1, 0, gb, nullptr, nullptr);

    // linear attention core
    attn_pass1<<<BATCH * NHEAD, 512>>>(qb, kb, Ab, zb);
    attn_pass2<<<dim3(BATCH * NHEAD, NTOK / 64), 256>>>(vb, gb, Ab, zb, yh, yl);

    // final projection
    gemm_mma<<<ggrid, 256, GSMEM_TOTAL>>>(yh, yl, WH(6), p_b, 0, 0, out, nullptr, nullptr);
}

// round 7
// speedup vs baseline: 2.5098x; 1.2396x over previous
#include <cuda_runtime.h>
#include <cuda_fp16.h>
#include <cuda_bf16.h>
#include <math.h>
#include <stdint.h>

// Problem constants
#define BATCH 4
#define NTOK 4096
#define DIM 1024
#define NHEAD 16
#define HD 64
#define MROWS (BATCH * NTOK)          // 16384
#define SCALE 0.125f                  // HD^-0.5
#define NCHUNK 4                      // attn_pass1 token-range split

// ---------------------------------------------------------------------------
// Scratch buffers
// ---------------------------------------------------------------------------
__device__ __half g_x_hi [MROWS * DIM];
__device__ __half g_x_lo [MROWS * DIM];
__device__ __half g_hq_hi[MROWS * DIM];
__device__ __half g_hq_lo[MROWS * DIM];
__device__ __half g_hk_hi[MROWS * DIM];
__device__ __half g_hk_lo[MROWS * DIM];
__device__ __half g_y_hi [MROWS * DIM];
__device__ __half g_y_lo [MROWS * DIM];
__device__ float g_q [MROWS * DIM];
__device__ float g_k [MROWS * DIM];
__device__ float g_v [MROWS * DIM];
__device__ float g_g [MROWS * DIM];
__device__ float g_A [BATCH * NHEAD * HD * HD];
__device__ float g_z [BATCH * NHEAD * HD];
__device__ float g_Ap[NCHUNK * BATCH * NHEAD * HD * HD];   // partial A
__device__ float g_zp[NCHUNK * BATCH * NHEAD * HD];        // partial z
__device__ __half g_w_h [7 * DIM * DIM];   // fp16 weights

// ---------------------------------------------------------------------------
// PTX helpers (sm_80+ portable)
// ---------------------------------------------------------------------------
__device__ __forceinline__ uint32_t smem_u32(const void* p) {
    uint32_t a;
    asm("{ .reg .u64 t; cvta.to.shared.u64 t, %1; cvt.u32.u64 %0, t; }" : "=r"(a) : "l"(p));
    return a;
}
#define SWZ(o) ((o) ^ (((o) >> 3) & 0x70))

__device__ __forceinline__ void cp16(uint32_t saddr, const void* g) {
    asm volatile("cp.async.cg.shared.global [%0], [%1], 16;" :: "r"(saddr), "l"(g));
}
#define CP_COMMIT() asm volatile("cp.async.commit_group;" ::: "memory")
#define CP_WAIT(N)  asm volatile("cp.async.wait_group %0;" :: "n"(N) : "memory")

#define LDSM4(r, a) \
    asm volatile("ldmatrix.sync.aligned.m8n8.x4.shared.b16 {%0,%1,%2,%3}, [%4];" \
        : "=r"((r)[0]), "=r"((r)[1]), "=r"((r)[2]), "=r"((r)[3]) : "r"(a))

#define MMA16816F(c, a, b) \
    asm volatile("mma.sync.aligned.m16n8k16.row.col.f32.f16.f16.f32 " \
        "{%0,%1,%2,%3}, {%4,%5,%6,%7}, {%8,%9}, {%0,%1,%2,%3};" \
        : "+f"((c)[0]), "+f"((c)[1]), "+f"((c)[2]), "+f"((c)[3]) \
        : "r"((a)[0]), "r"((a)[1]), "r"((a)[2]), "r"((a)[3]), \
          "r"((b)[0]), "r"((b)[1]))

// ---------------------------------------------------------------------------
// Activations
// ---------------------------------------------------------------------------
__device__ __forceinline__ float gelu_f(float x) {
    return 0.5f * x * (1.0f + erff(x * 0.70710678118654752440f));
}
__device__ __forceinline__ float softplus_f(float x) {
    return fmaxf(x, 0.0f) + log1pf(__expf(-fabsf(x)));
}
__device__ __forceinline__ uint32_t pack2h(float a, float b) {
    __half2 h = __halves2half2(__float2half_rn(a), __float2half_rn(b));
    return *(uint32_t*)&h;
}

// ---------------------------------------------------------------------------
// Split fp32 activations -> fp16 hi/lo pair
// ---------------------------------------------------------------------------
__global__ __launch_bounds__(256)
void split_act(const float* __restrict__ src, __half* __restrict__ hi,
               __half* __restrict__ lo, int n4)
{
    const int stride = gridDim.x * blockDim.x;
    for (int i = blockIdx.x * blockDim.x + threadIdx.x; i < n4; i += stride) {
        float4 v = ((const float4*)src)[i];
        float h0f = __half2float(__float2half_rn(v.x));
        float h1f = __half2float(__float2half_rn(v.y));
        float h2f = __half2float(__float2half_rn(v.z));
        float h3f = __half2float(__float2half_rn(v.w));
        uint2 hp, lp;
        hp.x = pack2h(v.x, v.y);
        hp.y = pack2h(v.z, v.w);
        lp.x = pack2h(v.x - h0f, v.y - h1f);
        lp.y = pack2h(v.z - h2f, v.w - h3f);
        ((uint2*)hi)[i] = hp;
        ((uint2*)lo)[i] = lp;
    }
}

// fp32 weight -> fp16
__global__ __launch_bounds__(256)
void conv_w(const float* __restrict__ src, __half* __restrict__ dst, int n4)
{
    const int stride = gridDim.x * blockDim.x;
    for (int i = blockIdx.x * blockDim.x + threadIdx.x; i < n4; i += stride) {
        float4 v = ((const float4*)src)[i];
        uint2 d;
        d.x = pack2h(v.x, v.y);
        d.y = pack2h(v.z, v.w);
        ((uint2*)dst)[i] = d;
    }
}

// ---------------------------------------------------------------------------
// HMMA fp16 2-term GEMM (unchanged from R6 — at HMMA pipe ceiling)
// ---------------------------------------------------------------------------
#define TILE_B 16384
#define STAGE_B (3 * TILE_B)
#define NSTAGE 2
#define GSMEM_TOTAL (NSTAGE * STAGE_B)   // 98304

__global__ __launch_bounds__(256, 2)
void gemm_mma(const __half* __restrict__ Ahi, const __half* __restrict__ Alo,
              const __half* __restrict__ Wh,
              const float* __restrict__ bias, int act, int outmode,
              float* __restrict__ Cf, __half* __restrict__ Chi,
              __half* __restrict__ Clo)
{
    extern __shared__ char smem[];
    const uint32_t sb = smem_u32(smem);
    const int t    = threadIdx.x;
    const int lane = t & 31;
    const int w    = t >> 5;
    const int wm   = w & 3;
    const int wn   = w >> 2;
    const int m0   = blockIdx.y * 128;
    const int n0   = blockIdx.x * 128;

    const int lrow = t >> 3;
    const int lu   = t & 7;

    auto issue = [&](int stage, int kc) {
        const uint32_t sbase = sb + stage * STAGE_B;
        const int kbase = kc * 64 + lu * 8;
#pragma unroll
        for (int i = 0; i < 4; i++) {
            const int row = lrow + i * 32;
            const uint32_t soff = SWZ((uint32_t)(row * 128 + lu * 16));
            const size_t aoff = (size_t)(m0 + row) * DIM + kbase;
            const size_t woff = (size_t)(n0 + row) * DIM + kbase;
            cp16(sbase + soff,              Ahi + aoff);
            cp16(sbase + TILE_B + soff,     Alo + aoff);
            cp16(sbase + 2 * TILE_B + soff, Wh  + woff);
        }
        CP_COMMIT();
    };

    issue(0, 0);
    issue(1, 1);

    float acc[2][8][4];
#pragma unroll
    for (int im = 0; im < 2; im++)
#pragma unroll
        for (int in = 0; in < 8; in++)
#pragma unroll
            for (int j = 0; j < 4; j++) acc[im][in][j] = 0.0f;

    const int g  = lane >> 3;
    const int rr = lane & 7;

    for (int kc = 0; kc < 16; kc++) {
        const int st_idx = kc & 1;
        if (kc == 15) { CP_WAIT(0); } else { CP_WAIT(1); }
        __syncthreads();

        const uint32_t st = sb + st_idx * STAGE_B;
#pragma unroll
        for (int kk = 0; kk < 4; kk++) {
            const int ku = kk * 2 + (g >> 1);
            uint32_t ah[2][4], al[2][4];
#pragma unroll
            for (int im = 0; im < 2; im++) {
                const int row = wm * 32 + im * 16 + (g & 1) * 8 + rr;
                const uint32_t off = SWZ((uint32_t)(row * 128 + ku * 16));
                LDSM4(ah[im], st + off);
                LDSM4(al[im], st + TILE_B + off);
            }
            uint32_t bh[8][2];
#pragma unroll
            for (int in2 = 0; in2 < 4; in2++) {
                const int row = wn * 64 + in2 * 16 + (g & 1) * 8 + rr;
                const uint32_t off = SWZ((uint32_t)(row * 128 + ku * 16));
                uint32_t qh[4];
                LDSM4(qh, st + 2 * TILE_B + off);
                bh[2 * in2][0] = qh[0]; bh[2 * in2][1] = qh[2];
                bh[2 * in2 + 1][0] = qh[1]; bh[2 * in2 + 1][1] = qh[3];
            }
#pragma unroll
            for (int im = 0; im < 2; im++)
#pragma unroll
                for (int in = 0; in < 8; in++) {
                    MMA16816F(acc[im][in], ah[im], bh[in]);
                    MMA16816F(acc[im][in], al[im], bh[in]);
                }
        }

        if (kc + 2 < 16) {
            __syncthreads();
            issue(st_idx, kc + 2);
        }
    }

    const int r0 = lane >> 2;
    const int c0 = (lane & 3) * 2;
#pragma unroll
    for (int im = 0; im < 2; im++) {
#pragma unroll
        for (int in = 0; in < 8; in++) {
            const int ncol = n0 + wn * 64 + in * 8 + c0;
            const float b0 = __ldg(&bias[ncol]);
            const float b1 = __ldg(&bias[ncol + 1]);
#pragma unroll
            for (int half = 0; half < 2; half++) {
                const int mrow = m0 + wm * 32 + im * 16 + r0 + half * 8;
                float v0 = acc[im][in][half * 2]     + b0;
                float v1 = acc[im][in][half * 2 + 1] + b1;
                if (act == 1)      { v0 = gelu_f(v0);     v1 = gelu_f(v1); }
                else if (act == 2) { v0 = softplus_f(v0); v1 = softplus_f(v1); }
                if (outmode == 0) {
                    *(float2*)(Cf + (size_t)mrow * DIM + ncol) = make_float2(v0, v1);
                } else {
                    __half h0 = __float2half_rn(v0);
                    __half h1 = __float2half_rn(v1);
                    __half l0 = __float2half_rn(v0 - __half2float(h0));
                    __half l1 = __float2half_rn(v1 - __half2float(h1));
                    *(__half2*)(Chi + (size_t)mrow * DIM + ncol) = __halves2half2(h0, h1);
                    *(__half2*)(Clo + (size_t)mrow * DIM + ncol) = __halves2half2(l0, l1);
                }
            }
        }
    }
}

// ---------------------------------------------------------------------------
// Attention pass 1 (partial): grid (64 bh, NCHUNK), each does NTOK/NCHUNK tokens
// ---------------------------------------------------------------------------
__global__ __launch_bounds__(512)
void attn_pass1p(const float* __restrict__ q, const float* __restrict__ k,
                 float* __restrict__ Ap, float* __restrict__ Zp)
{
    const int bh = blockIdx.x;
    const int ch = blockIdx.y;
    const int b  = bh >> 4;
    const int h  = bh & 15;
    const float* qb = q + (size_t)b * NTOK * DIM + h * HD;
    const float* kb = k + (size_t)b * NTOK * DIM + h * HD;

    __shared__ float qs[64][64];
    __shared__ float ks[64][64];
    __shared__ float ksum[64];

    const int t  = threadIdx.x;
    const int n  = t >> 3;
    const int m0 = (t & 7) << 3;
    const int lr = t >> 3;
    const int lc = (t & 7) << 3;

    float acc[8] = {0, 0, 0, 0, 0, 0, 0, 0};
    float zacc = 0.0f;
    const bool zowner = ((t & 7) == 0);

    const int cbeg = ch * (NTOK / NCHUNK);
    const int cend = cbeg + (NTOK / NCHUNK);
    for (int c0 = cbeg; c0 < cend; c0 += 64) {
        const float* qrow = qb + (size_t)(c0 + lr) * DIM + lc;
        const float* krow = kb + (size_t)(c0 + lr) * DIM + lc;
        float4 qa = *(const float4*)(qrow);
        float4 qc = *(const float4*)(qrow + 4);
        float4 ka = *(const float4*)(krow);
        float4 kc = *(const float4*)(krow + 4);
        __syncthreads();
        *(float4*)&qs[lr][lc]     = qa;
        *(float4*)&qs[lr][lc + 4] = qc;
        *(float4*)&ks[lr][lc]     = ka;
        *(float4*)&ks[lr][lc + 4] = kc;
        __syncthreads();
        if (t < 64) {
            float s = 0.0f;
#pragma unroll
            for (int m = 0; m < 64; m++) s += ks[t][(m + t) & 63];
            ksum[t] = s;
        }
        __syncthreads();

#pragma unroll 4
        for (int c = 0; c < 64; c++) {
            float qv = qs[c][n];
            float4 k4a = *(const float4*)&ks[c][m0];
            float4 k4b = *(const float4*)&ks[c][m0 + 4];
            acc[0] += qv * k4a.x; acc[1] += qv * k4a.y;
            acc[2] += qv * k4a.z; acc[3] += qv * k4a.w;
            acc[4] += qv * k4b.x; acc[5] += qv * k4b.y;
            acc[6] += qv * k4b.z; acc[7] += qv * k4b.w;
            if (zowner) zacc += qv * ksum[c];
        }
    }

    float* Abh = Ap + ((size_t)ch * 64 + bh) * HD * HD;
#pragma unroll
    for (int j = 0; j < 8; j++)
        Abh[(m0 + j) * HD + n] = acc[j];
    if (zowner)
        Zp[((size_t)ch * 64 + bh) * HD + n] = zacc;
}

// Reduce partials: 64 blocks x 256 threads
__global__ __launch_bounds__(256)
void attn_reduce(const float* __restrict__ Ap, const float* __restrict__ Zp,
                 float* __restrict__ gA, float* __restrict__ gZ)
{
    const int bh = blockIdx.x;
    const int t  = threadIdx.x;
    for (int i = t; i < HD * HD; i += 256) {
        float s = 0.0f;
#pragma unroll
        for (int c = 0; c < NCHUNK; c++)
            s += Ap[((size_t)c * 64 + bh) * HD * HD + i];
        gA[(size_t)bh * HD * HD + i] = s;
    }
    if (t < HD) {
        float s = 0.0f;
#pragma unroll
        for (int c = 0; c < NCHUNK; c++)
            s += Zp[((size_t)c * 64 + bh) * HD + t];
        gZ[bh * HD + t] = 1.0f / (SCALE * s + (float)DIM);
    }
}

// ---------------------------------------------------------------------------
// Attention pass 2 — writes scrambled gated output as fp16 hi/lo
// ---------------------------------------------------------------------------
__global__ __launch_bounds__(256)
void attn_pass2(const float* __restrict__ v, const float* __restrict__ gg,
                const float* __restrict__ gA, const float* __restrict__ gZ,
                __half* __restrict__ Yhi, __half* __restrict__ Ylo)
{
    const int bh = blockIdx.x;
    const int b  = bh >> 4;
    const int h  = bh & 15;
    const int c0 = blockIdx.y * 64;

    __shared__ float As[HD * HD];
    __shared__ float vs[64][64];
    __shared__ float zs[64];

    const int t = threadIdx.x;

    const float4* Asrc = (const float4*)(gA + (size_t)bh * HD * HD);
#pragma unroll
    for (int i = t; i < HD * HD / 4; i += 256)
        ((float4*)As)[i] = Asrc[i];
    if (t < 64) zs[t] = gZ[bh * HD + t];

    {
        const int lr = t >> 2;
        const int lc = (t & 3) << 4;
        const float* vrow = v + (size_t)(b * NTOK + c0 + lr) * DIM + h * HD + lc;
        *(float4*)&vs[lr][lc]      = *(const float4*)(vrow);
        *(float4*)&vs[lr][lc + 4]  = *(const float4*)(vrow + 4);
        *(float4*)&vs[lr][lc + 8]  = *(const float4*)(vrow + 8);
        *(float4*)&vs[lr][lc + 12] = *(const float4*)(vrow + 12);
    }
    __syncthreads();

    const int nloc = t & 63;
    const int dgrp = t >> 6;

    for (int d = dgrp; d < 64; d += 4) {
        float accv = 0.0f;
#pragma unroll
        for (int m = 0; m < 64; m++)
            accv += As[m * 64 + nloc] * vs[d][m];
        const int tok = c0 + d;
        float val = (SCALE * accv + vs[d][nloc]) * zs[nloc];
        val *= gg[(size_t)(b * NTOK + tok) * DIM + h * HD + nloc];
        const int row = b * NTOK + h * 256 + (tok >> 4);
        const int col = ((tok & 15) << 6) + nloc;
        __half hi = __float2half_rn(val);
        __half lo = __float2half_rn(val - __half2float(hi));
        Yhi[(size_t)row * DIM + col] = hi;
        Ylo[(size_t)row * DIM + col] = lo;
    }
}

// ---------------------------------------------------------------------------
// Launch — stream-forked DAG with R6 GEMM core
// ---------------------------------------------------------------------------
extern "C" void kernel_launch(void* const* d_in, const int* in_sizes, int n_in,
                              void* d_out, int out_size)
{
    const float* x    = (const float*)d_in[0];
    const float* q_w1 = (const float*)d_in[1];
    const float* q_b1 = (const float*)d_in[2];
    const float* q_w2 = (const float*)d_in[3];
    const float* q_b2 = (const float*)d_in[4];
    const float* k_w1 = (const float*)d_in[5];
    const float* k_b1 = (const float*)d_in[6];
    const float* k_w2 = (const float*)d_in[7];
    const float* k_b2 = (const float*)d_in[8];
    const float* v_w  = (const float*)d_in[9];
    const float* v_b  = (const float*)d_in[10];
    const float* g_w  = (const float*)d_in[11];
    const float* g_b  = (const float*)d_in[12];
    const float* p_w  = (const float*)d_in[13];
    const float* p_b  = (const float*)d_in[14];
    float* out = (float*)d_out;

    __half *xh, *xl, *hqh, *hql, *hkh, *hkl, *yh, *yl, *wh;
    float *qb, *kb, *vb, *gb, *Ab, *zb, *Apb, *zpb;
    cudaGetSymbolAddress((void**)&xh,  g_x_hi);
    cudaGetSymbolAddress((void**)&xl,  g_x_lo);
    cudaGetSymbolAddress((void**)&hqh, g_hq_hi);
    cudaGetSymbolAddress((void**)&hql, g_hq_lo);
    cudaGetSymbolAddress((void**)&hkh, g_hk_hi);
    cudaGetSymbolAddress((void**)&hkl, g_hk_lo);
    cudaGetSymbolAddress((void**)&yh,  g_y_hi);
    cudaGetSymbolAddress((void**)&yl,  g_y_lo);
    cudaGetSymbolAddress((void**)&wh,  g_w_h);
    cudaGetSymbolAddress((void**)&qb,  g_q);
    cudaGetSymbolAddress((void**)&kb,  g_k);
    cudaGetSymbolAddress((void**)&vb,  g_v);
    cudaGetSymbolAddress((void**)&gb,  g_g);
    cudaGetSymbolAddress((void**)&Ab,  g_A);
    cudaGetSymbolAddress((void**)&zb,  g_z);
    cudaGetSymbolAddress((void**)&Apb, g_Ap);
    cudaGetSymbolAddress((void**)&zpb, g_zp);

    static bool init_done = false;
    static cudaStream_t s1, s2, s3;
    static cudaEvent_t ev_x, ev_k, ev_v, ev_g;
    if (!init_done) {
        cudaFuncSetAttribute(gemm_mma, cudaFuncAttributeMaxDynamicSharedMemorySize, GSMEM_TOTAL);
        cudaStreamCreateWithFlags(&s1, cudaStreamNonBlocking);
        cudaStreamCreateWithFlags(&s2, cudaStreamNonBlocking);
        cudaStreamCreateWithFlags(&s3, cudaStreamNonBlocking);
        cudaEventCreateWithFlags(&ev_x, cudaEventDisableTiming);
        cudaEventCreateWithFlags(&ev_k, cudaEventDisableTiming);
        cudaEventCreateWithFlags(&ev_v, cudaEventDisableTiming);
        cudaEventCreateWithFlags(&ev_g, cudaEventDisableTiming);
        init_done = true;
    }

    const int WSZ = DIM * DIM;
#define WH(i) (wh + (size_t)(i) * WSZ)

    dim3 ggrid(DIM / 128, MROWS / 128);   // (8, 128)

    // stream0: split x, then fork
    split_act<<<1184, 256>>>(x, xh, xl, MROWS * DIM / 4);
    cudaEventRecord(ev_x, 0);

    // --- s1: k path ---
    cudaStreamWaitEvent(s1, ev_x, 0);
    conv_w<<<592, 256, 0, s1>>>(k_w1, WH(2), WSZ / 4);
    gemm_mma<<<ggrid, 256, GSMEM_TOTAL, s1>>>(xh, xl, WH(2), k_b1, 1, 1, nullptr, hkh, hkl);
    conv_w<<<592, 256, 0, s1>>>(k_w2, WH(3), WSZ / 4);
    gemm_mma<<<ggrid, 256, GSMEM_TOTAL, s1>>>(hkh, hkl, WH(3), k_b2, 2, 0, kb, nullptr, nullptr);
    cudaEventRecord(ev_k, s1);

    // --- s2: v ---
    cudaStreamWaitEvent(s2, ev_x, 0);
    conv_w<<<592, 256, 0, s2>>>(v_w, WH(4), WSZ / 4);
    gemm_mma<<<ggrid, 256, GSMEM_TOTAL, s2>>>(xh, xl, WH(4), v_b, 1, 0, vb, nullptr, nullptr);
    cudaEventRecord(ev_v, s2);

    // --- s3: g ---
    cudaStreamWaitEvent(s3, ev_x, 0);
    conv_w<<<592, 256, 0, s3>>>(g_w, WH(5), WSZ / 4);
    gemm_mma<<<ggrid, 256, GSMEM_TOTAL, s3>>>(xh, xl, WH(5), g_b, 1, 0, gb, nullptr, nullptr);
    cudaEventRecord(ev_g, s3);

    // --- stream0: q path + p_w conversion ---
    conv_w<<<592, 256>>>(q_w1, WH(0), WSZ / 4);
    gemm_mma<<<ggrid, 256, GSMEM_TOTAL>>>(xh, xl, WH(0), q_b1, 1, 1, nullptr, hqh, hql);
    conv_w<<<592, 256>>>(q_w2, WH(1), WSZ / 4);
    gemm_mma<<<ggrid, 256, GSMEM_TOTAL>>>(hqh, hql, WH(1), q_b2, 2, 0, qb, nullptr, nullptr);
    conv_w<<<592, 256>>>(p_w, WH(6), WSZ / 4);

    // join k for attention pass 1 (chunked, then reduce)
    cudaStreamWaitEvent(0, ev_k, 0);
    attn_pass1p<<<dim3(BATCH * NHEAD, NCHUNK), 512>>>(qb, kb, Apb, zpb);
    attn_reduce<<<BATCH * NHEAD, 256>>>(Apb, zpb, Ab, zb);

    // join v, g for pass 2
    cudaStreamWaitEvent(0, ev_v, 0);
    cudaStreamWaitEvent(0, ev_g, 0);
    attn_pass2<<<dim3(BATCH * NHEAD, NTOK / 64), 256>>>(vb, gb, Ab, zb, yh, yl);

    // final projection
    gemm_mma<<<ggrid, 256, GSMEM_TOTAL>>>(yh, yl, WH(6), p_b, 0, 0, out, nullptr, nullptr);
}